// round 5
// baseline (speedup 1.0000x reference)
#include <cuda_runtime.h>
#include <cstdint>

// Problem constants (fixed by setup_inputs)
#define BB    4
#define NP    2000
#define NG    100
#define MH    1024
#define MW    1024
#define PCAP  66
#define NCAP  134
#define TROIS 200
#define MS1   28
#define MS2   28
#define MPIX  (MS1*MS2)

// Output layout (flattened tuple, all float32):
//   rois    [BB,TROIS,4]        at 0
//   class   [BB,TROIS]          at BB*TROIS*4
//   deltas  [BB,TROIS,4]        at BB*TROIS*5
//   masks   [BB,TROIS,28,28]    at BB*TROIS*9
#define OFF_CLS   (BB*TROIS*4)
#define OFF_DEL   (BB*TROIS*4 + BB*TROIS)
#define OFF_MASK  (BB*TROIS*4 + BB*TROIS + BB*TROIS*4)

// Inter-kernel scratch (no allocations allowed -> __device__ globals)
__device__ int   d_mask_kind;              // 0=uint8, 1=int32, 2=float32
__device__ int   d_pos_idx[BB][PCAP];
__device__ int   d_num_pos[BB];
__device__ int   d_neg_idx[BB][NCAP];
__device__ int   d_num_neg[BB];
__device__ int   d_gt_assign[BB][PCAP];
__device__ float d_pos_roi[BB][PCAP][4];

// IEEE-exact IoU matching XLA op order (immune to --use_fast_math).
__device__ __forceinline__ float iou_pair(float py1,float px1,float py2,float px2,float a1,
                                          float gy1,float gx1,float gy2,float gx2,float a2){
    float y1 = fmaxf(py1, gy1);
    float x1 = fmaxf(px1, gx1);
    float y2 = fminf(py2, gy2);
    float x2 = fminf(px2, gx2);
    float dy = fmaxf(__fsub_rn(y2, y1), 0.0f);
    float dx = fmaxf(__fsub_rn(x2, x1), 0.0f);
    float inter = __fmul_rn(dy, dx);
    float uni = __fsub_rn(__fadd_rn(a1, a2), inter);
    return __fdiv_rn(inter, uni > 0.0f ? uni : 1.0f);
}

__device__ __forceinline__ float box_area(float y1, float x1, float y2, float x2) {
    return __fmul_rn(__fsub_rn(y2, y1), __fsub_rn(x2, x1));
}

// ---------------------------------------------------------------------------
// Kernel A: probe how the bool gt_masks tensor was materialized.
// ---------------------------------------------------------------------------
__global__ void k_detect_kind(const unsigned int* __restrict__ masks) {
    if (threadIdx.x == 0 && blockIdx.x == 0) {
        int kind = 1; // default int32
        for (int i = 0; i < 4096; i++) {
            unsigned int w = masks[i];
            if (w == 0x3F800000u) { kind = 2; break; }
            if (w != 0u && w != 1u) { kind = 0; break; }
        }
        d_mask_kind = kind;
    }
}

// ---------------------------------------------------------------------------
// Kernel B: per-image flags (pos/neg per proposal) + deterministic selection
// ---------------------------------------------------------------------------
__global__ void k_flags_select(const float* __restrict__ props,
                               const int*   __restrict__ gtc,
                               const float* __restrict__ gtb) {
    int b = blockIdx.x;
    __shared__ float s_g[NG][4];
    __shared__ float s_area[NG];
    __shared__ unsigned char s_ok[NG];      // gt_valid && cls>0
    __shared__ unsigned char s_crowd[NG];   // gt_valid && cls<0
    __shared__ unsigned char s_flag[NP];    // 0 none, 1 pos, 2 neg

    for (int g = threadIdx.x; g < NG; g += blockDim.x) {
        const float* gp = gtb + ((size_t)b * NG + g) * 4;
        float y1 = gp[0], x1 = gp[1], y2 = gp[2], x2 = gp[3];
        s_g[g][0] = y1; s_g[g][1] = x1; s_g[g][2] = y2; s_g[g][3] = x2;
        bool valid = (y1 != 0.0f) || (x1 != 0.0f) || (y2 != 0.0f) || (x2 != 0.0f);
        int cls = gtc[(size_t)b * NG + g];
        s_ok[g]    = (valid && cls > 0) ? 1 : 0;
        s_crowd[g] = (valid && cls < 0) ? 1 : 0;
        s_area[g]  = box_area(y1, x1, y2, x2);
    }
    __syncthreads();

    for (int n = threadIdx.x; n < NP; n += blockDim.x) {
        const float* pp = props + ((size_t)b * NP + n) * 4;
        float py1 = pp[0], px1 = pp[1], py2 = pp[2], px2 = pp[3];
        bool pv = (py1 != 0.0f) || (px1 != 0.0f) || (py2 != 0.0f) || (px2 != 0.0f);
        float a1 = box_area(py1, px1, py2, px2);
        float max_ok = -1.0f, max_crowd = -1.0f;
        for (int g = 0; g < NG; g++) {
            if (!(s_ok[g] | s_crowd[g])) continue;
            float v = iou_pair(py1, px1, py2, px2, a1,
                               s_g[g][0], s_g[g][1], s_g[g][2], s_g[g][3], s_area[g]);
            if (s_ok[g])    max_ok    = fmaxf(max_ok, v);
            if (s_crowd[g]) max_crowd = fmaxf(max_crowd, v);
        }
        unsigned char f = 0;
        if (pv) {
            if (max_ok >= 0.5f) f = 1;
            else if (max_crowd < 0.001f) f = 2;
        }
        s_flag[n] = f;
    }
    __syncthreads();

    if (threadIdx.x == 0) {
        int np = 0, nn = 0;
        for (int n = 0; n < NP; n++) {
            unsigned char f = s_flag[n];
            if (f == 1) { if (np < PCAP) d_pos_idx[b][np++] = n; }
            else if (f == 2) { if (nn < NCAP) d_neg_idx[b][nn++] = n; }
        }
        // neg_target: XLA lowers x/0.33f to x * rn(1/0.33f). For np=66 this
        // gives 66 * 3.03030300140381f = 200.0 exactly -> int 200 -> 134.
        // (Strict rn division would give 199 -> 133: ONE fewer negative slot,
        //  which was exactly the observed per-image mismatch.)
        float recip = __fdiv_rn(1.0f, 0.33f);
        int neg_target = (int)__fmul_rn((float)np, recip) - np;
        if (neg_target < 0) neg_target = 0;
        d_num_pos[b] = np;
        d_num_neg[b] = (nn < neg_target) ? nn : neg_target;
    }
}

// ---------------------------------------------------------------------------
// Kernel C: rois / class ids / deltas for all 200 slots; gt_assign per positive
// ---------------------------------------------------------------------------
__global__ void k_outputs(const float* __restrict__ props,
                          const int*   __restrict__ gtc,
                          const float* __restrict__ gtb,
                          float* __restrict__ out) {
    int b = blockIdx.x;
    __shared__ float s_g[NG][4];
    __shared__ float s_area[NG];
    __shared__ int   s_cls[NG];
    __shared__ unsigned char s_ok[NG];

    for (int g = threadIdx.x; g < NG; g += blockDim.x) {
        const float* gp = gtb + ((size_t)b * NG + g) * 4;
        float y1 = gp[0], x1 = gp[1], y2 = gp[2], x2 = gp[3];
        s_g[g][0] = y1; s_g[g][1] = x1; s_g[g][2] = y2; s_g[g][3] = x2;
        bool valid = (y1 != 0.0f) || (x1 != 0.0f) || (y2 != 0.0f) || (x2 != 0.0f);
        int cls = gtc[(size_t)b * NG + g];
        s_cls[g]  = cls;
        s_ok[g]   = (valid && cls > 0) ? 1 : 0;
        s_area[g] = box_area(y1, x1, y2, x2);
    }
    __syncthreads();

    int np = d_num_pos[b];
    int nn = d_num_neg[b];
    float* rois_out = out + (size_t)b * TROIS * 4;
    float* cls_out  = out + OFF_CLS + (size_t)b * TROIS;
    float* del_out  = out + OFF_DEL + (size_t)b * TROIS * 4;

    int t = threadIdx.x;
    if (t < PCAP) {
        float r0 = 0, r1 = 0, r2 = 0, r3 = 0;
        float c = 0, d0 = 0, d1 = 0, d2 = 0, d3 = 0;
        int ga = 0;
        if (t < np) {
            int n = d_pos_idx[b][t];
            const float* pp = props + ((size_t)b * NP + n) * 4;
            r0 = pp[0]; r1 = pp[1]; r2 = pp[2]; r3 = pp[3];
            float a1 = box_area(r0, r1, r2, r3);
            float best = -2.0f;
            for (int g = 0; g < NG; g++) {
                float v = s_ok[g] ? iou_pair(r0, r1, r2, r3, a1,
                                             s_g[g][0], s_g[g][1], s_g[g][2], s_g[g][3],
                                             s_area[g])
                                  : -1.0f;
                if (v > best) { best = v; ga = g; }
            }
            float gy1 = s_g[ga][0], gx1 = s_g[ga][1], gy2 = s_g[ga][2], gx2 = s_g[ga][3];
            float h  = __fsub_rn(r2, r0);
            float w  = __fsub_rn(r3, r1);
            float gh = __fsub_rn(gy2, gy1);
            float gw = __fsub_rn(gx2, gx1);
            float cy  = __fadd_rn(r0,  __fmul_rn(0.5f, h));
            float cx  = __fadd_rn(r1,  __fmul_rn(0.5f, w));
            float gcy = __fadd_rn(gy1, __fmul_rn(0.5f, gh));
            float gcx = __fadd_rn(gx1, __fmul_rn(0.5f, gw));
            d0 = __fdiv_rn(__fdiv_rn(__fsub_rn(gcy, cy), h), 0.1f);
            d1 = __fdiv_rn(__fdiv_rn(__fsub_rn(gcx, cx), w), 0.1f);
            d2 = __fdiv_rn((float)log((double)__fdiv_rn(gh, h)), 0.2f);
            d3 = __fdiv_rn((float)log((double)__fdiv_rn(gw, w)), 0.2f);
            c = (float)s_cls[ga];
        }
        d_gt_assign[b][t] = ga;
        d_pos_roi[b][t][0] = r0; d_pos_roi[b][t][1] = r1;
        d_pos_roi[b][t][2] = r2; d_pos_roi[b][t][3] = r3;
        rois_out[t * 4 + 0] = r0; rois_out[t * 4 + 1] = r1;
        rois_out[t * 4 + 2] = r2; rois_out[t * 4 + 3] = r3;
        cls_out[t] = c;
        del_out[t * 4 + 0] = d0; del_out[t * 4 + 1] = d1;
        del_out[t * 4 + 2] = d2; del_out[t * 4 + 3] = d3;
    } else if (t < TROIS) {
        int j = t - PCAP;
        float r0 = 0, r1 = 0, r2 = 0, r3 = 0;
        if (j < nn) {
            int n = d_neg_idx[b][j];
            const float* pp = props + ((size_t)b * NP + n) * 4;
            r0 = pp[0]; r1 = pp[1]; r2 = pp[2]; r3 = pp[3];
        }
        rois_out[t * 4 + 0] = r0; rois_out[t * 4 + 1] = r1;
        rois_out[t * 4 + 2] = r2; rois_out[t * 4 + 3] = r3;
        cls_out[t] = 0.0f;
        del_out[t * 4 + 0] = 0.0f; del_out[t * 4 + 1] = 0.0f;
        del_out[t * 4 + 2] = 0.0f; del_out[t * 4 + 3] = 0.0f;
    }
}

// ---------------------------------------------------------------------------
// Kernel D: mask targets. One block per (image, roi-slot); 784 pixels each.
// ---------------------------------------------------------------------------
__device__ __forceinline__ float load_mask_val(const void* masks, int kind, size_t idx) {
    if (kind == 0) return (float)((const unsigned char*)masks)[idx];
    if (kind == 1) return (float)((const int*)masks)[idx];
    return ((const float*)masks)[idx];
}

__global__ void k_masks(const void* __restrict__ masks, float* __restrict__ out) {
    int slot = blockIdx.x % TROIS;
    int b    = blockIdx.x / TROIS;
    float* mout = out + OFF_MASK + ((size_t)(b * TROIS + slot)) * MPIX;

    int np = d_num_pos[b];
    if (slot >= np || slot >= PCAP) {
        for (int p = threadIdx.x; p < MPIX; p += blockDim.x) mout[p] = 0.0f;
        return;
    }
    int kind = d_mask_kind;
    float y1 = d_pos_roi[b][slot][0];
    float x1 = d_pos_roi[b][slot][1];
    float y2 = d_pos_roi[b][slot][2];
    float x2 = d_pos_roi[b][slot][3];
    int g = d_gt_assign[b][slot];
    float dy = __fsub_rn(y2, y1);
    float dx = __fsub_rn(x2, x1);

    for (int p = threadIdx.x; p < MPIX; p += blockDim.x) {
        int i = p / MS2;
        int j = p % MS2;
        // ys = (y1 + (y2-y1)*i/27) * 1023  — exact jnp op order, IEEE rn
        float ys = __fmul_rn(__fadd_rn(y1, __fdiv_rn(__fmul_rn(dy, (float)i), 27.0f)), 1023.0f);
        float xs = __fmul_rn(__fadd_rn(x1, __fdiv_rn(__fmul_rn(dx, (float)j), 27.0f)), 1023.0f);

        float y0f = fminf(fmaxf(floorf(ys), 0.0f), 1023.0f);
        float x0f = fminf(fmaxf(floorf(xs), 0.0f), 1023.0f);
        int y0 = (int)y0f;
        int x0 = (int)x0f;
        int y1i = (int)fminf(__fadd_rn(y0f, 1.0f), 1023.0f);
        int x1i = (int)fminf(__fadd_rn(x0f, 1.0f), 1023.0f);
        float wy = __fsub_rn(ys, y0f);
        float wx = __fsub_rn(xs, x0f);
        float oy = __fsub_rn(1.0f, wy);
        float ox = __fsub_rn(1.0f, wx);

        size_t base_b = (size_t)b * MH;
        size_t row0 = (base_b + (size_t)y0)  * MW;
        size_t row1 = (base_b + (size_t)y1i) * MW;
        float m00 = load_mask_val(masks, kind, (row0 + x0)  * NG + g);
        float m01 = load_mask_val(masks, kind, (row0 + x1i) * NG + g);
        float m10 = load_mask_val(masks, kind, (row1 + x0)  * NG + g);
        float m11 = load_mask_val(masks, kind, (row1 + x1i) * NG + g);

        float t0 = __fmul_rn(__fmul_rn(m00, oy), ox);
        float t1 = __fmul_rn(__fmul_rn(m01, oy), wx);
        float t2 = __fmul_rn(__fmul_rn(m10, wy), ox);
        float t3 = __fmul_rn(__fmul_rn(m11, wy), wx);
        float val = __fadd_rn(__fadd_rn(__fadd_rn(t0, t1), t2), t3);
        mout[p] = rintf(val);   // round-half-even, matches jnp.round
    }
}

extern "C" void kernel_launch(void* const* d_in, const int* in_sizes, int n_in,
                              void* d_out, int out_size) {
    const float* props = (const float*)d_in[0];
    const int*   gtc   = (const int*)d_in[1];
    const float* gtb   = (const float*)d_in[2];
    const void*  masks = d_in[3];
    float* out = (float*)d_out;

    k_detect_kind<<<1, 32>>>((const unsigned int*)masks);
    k_flags_select<<<BB, 256>>>(props, gtc, gtb);
    k_outputs<<<BB, 256>>>(props, gtc, gtb, out);
    k_masks<<<BB * TROIS, 256>>>(masks, out);
}

// round 7
// speedup vs baseline: 1.6829x; 1.6829x over previous
#include <cuda_runtime.h>
#include <cstdint>

// Problem constants (fixed by setup_inputs)
#define BB    4
#define NP    2000
#define NG    100
#define MH    1024
#define MW    1024
#define PCAP  66
#define NCAP  134
#define TROIS 200
#define MS1   28
#define MS2   28
#define MPIX  (MS1*MS2)

// Output layout (flattened tuple, all float32):
//   rois    [BB,TROIS,4]        at 0
//   class   [BB,TROIS]          at BB*TROIS*4
//   deltas  [BB,TROIS,4]        at BB*TROIS*5
//   masks   [BB,TROIS,28,28]    at BB*TROIS*9
#define OFF_CLS   (BB*TROIS*4)
#define OFF_DEL   (BB*TROIS*4 + BB*TROIS)
#define OFF_MASK  (BB*TROIS*4 + BB*TROIS + BB*TROIS*4)

// Inter-kernel scratch (no allocations allowed -> __device__ globals)
__device__ int   d_mask_kind;              // 0=uint8, 1=int32, 2=float32
__device__ int   d_pos_idx[BB][PCAP];
__device__ int   d_num_pos[BB];
__device__ int   d_neg_idx[BB][NCAP];
__device__ int   d_num_neg[BB];
__device__ int   d_gt_assign[BB][PCAP];
__device__ float d_pos_roi[BB][PCAP][4];

// IEEE-exact IoU matching XLA op order (immune to --use_fast_math).
__device__ __forceinline__ float iou_pair(float py1,float px1,float py2,float px2,float a1,
                                          float gy1,float gx1,float gy2,float gx2,float a2){
    float y1 = fmaxf(py1, gy1);
    float x1 = fmaxf(px1, gx1);
    float y2 = fminf(py2, gy2);
    float x2 = fminf(px2, gx2);
    float dy = fmaxf(__fsub_rn(y2, y1), 0.0f);
    float dx = fmaxf(__fsub_rn(x2, x1), 0.0f);
    float inter = __fmul_rn(dy, dx);
    float uni = __fsub_rn(__fadd_rn(a1, a2), inter);
    return __fdiv_rn(inter, uni > 0.0f ? uni : 1.0f);
}

__device__ __forceinline__ float box_area(float y1, float x1, float y2, float x2) {
    return __fmul_rn(__fsub_rn(y2, y1), __fsub_rn(x2, x1));
}

// ---------------------------------------------------------------------------
// Kernel A: probe how the bool gt_masks tensor was materialized — PARALLEL.
// flags bit0: saw 0x3F800000 (float32 one)   -> kind 2
// flags bit1: saw word not in {0,1,0x3F800000} (packed uint8) -> kind 0
// neither -> all words in {0,1} -> int32 -> kind 1
// (dtype is uniform, so any-over-window == first-decisive-word semantics)
// ---------------------------------------------------------------------------
__global__ void k_detect_kind(const unsigned int* __restrict__ masks) {
    __shared__ int s_flags;
    if (threadIdx.x == 0) s_flags = 0;
    __syncthreads();
    unsigned int w = masks[blockIdx.x * blockDim.x + threadIdx.x];
    int f = 0;
    if (w == 0x3F800000u) f |= 1;
    else if (w != 0u && w != 1u) f |= 2;
    // warp-level OR then one atomic per warp
    for (int o = 16; o > 0; o >>= 1) f |= __shfl_xor_sync(0xFFFFFFFFu, f, o);
    if ((threadIdx.x & 31) == 0 && f) atomicOr(&s_flags, f);
    __syncthreads();
    if (threadIdx.x == 0) {
        int fl = s_flags;
        // single block -> write directly
        d_mask_kind = (fl & 1) ? 2 : ((fl & 2) ? 0 : 1);
    }
}

// ---------------------------------------------------------------------------
// Kernel B: per-image flags (pos/neg per proposal) + deterministic selection
// ---------------------------------------------------------------------------
__global__ void k_flags_select(const float* __restrict__ props,
                               const int*   __restrict__ gtc,
                               const float* __restrict__ gtb) {
    int b = blockIdx.x;
    __shared__ float s_g[NG][4];
    __shared__ float s_area[NG];
    __shared__ unsigned char s_ok[NG];      // gt_valid && cls>0
    __shared__ unsigned char s_crowd[NG];   // gt_valid && cls<0
    __shared__ unsigned char s_flag[NP];    // 0 none, 1 pos, 2 neg

    for (int g = threadIdx.x; g < NG; g += blockDim.x) {
        const float* gp = gtb + ((size_t)b * NG + g) * 4;
        float y1 = gp[0], x1 = gp[1], y2 = gp[2], x2 = gp[3];
        s_g[g][0] = y1; s_g[g][1] = x1; s_g[g][2] = y2; s_g[g][3] = x2;
        bool valid = (y1 != 0.0f) || (x1 != 0.0f) || (y2 != 0.0f) || (x2 != 0.0f);
        int cls = gtc[(size_t)b * NG + g];
        s_ok[g]    = (valid && cls > 0) ? 1 : 0;
        s_crowd[g] = (valid && cls < 0) ? 1 : 0;
        s_area[g]  = box_area(y1, x1, y2, x2);
    }
    __syncthreads();

    for (int n = threadIdx.x; n < NP; n += blockDim.x) {
        const float* pp = props + ((size_t)b * NP + n) * 4;
        float py1 = pp[0], px1 = pp[1], py2 = pp[2], px2 = pp[3];
        bool pv = (py1 != 0.0f) || (px1 != 0.0f) || (py2 != 0.0f) || (px2 != 0.0f);
        float a1 = box_area(py1, px1, py2, px2);
        float max_ok = -1.0f, max_crowd = -1.0f;
        for (int g = 0; g < NG; g++) {
            if (!(s_ok[g] | s_crowd[g])) continue;
            float v = iou_pair(py1, px1, py2, px2, a1,
                               s_g[g][0], s_g[g][1], s_g[g][2], s_g[g][3], s_area[g]);
            if (s_ok[g])    max_ok    = fmaxf(max_ok, v);
            if (s_crowd[g]) max_crowd = fmaxf(max_crowd, v);
        }
        unsigned char f = 0;
        if (pv) {
            if (max_ok >= 0.5f) f = 1;
            else if (max_crowd < 0.001f) f = 2;
        }
        s_flag[n] = f;
    }
    __syncthreads();

    if (threadIdx.x == 0) {
        int np = 0, nn = 0;
        for (int n = 0; n < NP; n++) {
            unsigned char f = s_flag[n];
            if (f == 1) { if (np < PCAP) d_pos_idx[b][np++] = n; }
            else if (f == 2) { if (nn < NCAP) d_neg_idx[b][nn++] = n; }
        }
        // neg_target: XLA lowers x/0.33f to x * rn(1/0.33f). For np=66:
        // 66 * 3.03030300140381f = 200.0 exactly -> int 200 -> 134 negatives.
        float recip = __fdiv_rn(1.0f, 0.33f);
        int neg_target = (int)__fmul_rn((float)np, recip) - np;
        if (neg_target < 0) neg_target = 0;
        d_num_pos[b] = np;
        d_num_neg[b] = (nn < neg_target) ? nn : neg_target;
    }
}

// ---------------------------------------------------------------------------
// Kernel C: rois / class ids / deltas for all 200 slots; gt_assign per positive
// ---------------------------------------------------------------------------
__global__ void k_outputs(const float* __restrict__ props,
                          const int*   __restrict__ gtc,
                          const float* __restrict__ gtb,
                          float* __restrict__ out) {
    int b = blockIdx.x;
    __shared__ float s_g[NG][4];
    __shared__ float s_area[NG];
    __shared__ int   s_cls[NG];
    __shared__ unsigned char s_ok[NG];

    for (int g = threadIdx.x; g < NG; g += blockDim.x) {
        const float* gp = gtb + ((size_t)b * NG + g) * 4;
        float y1 = gp[0], x1 = gp[1], y2 = gp[2], x2 = gp[3];
        s_g[g][0] = y1; s_g[g][1] = x1; s_g[g][2] = y2; s_g[g][3] = x2;
        bool valid = (y1 != 0.0f) || (x1 != 0.0f) || (y2 != 0.0f) || (x2 != 0.0f);
        int cls = gtc[(size_t)b * NG + g];
        s_cls[g]  = cls;
        s_ok[g]   = (valid && cls > 0) ? 1 : 0;
        s_area[g] = box_area(y1, x1, y2, x2);
    }
    __syncthreads();

    int np = d_num_pos[b];
    int nn = d_num_neg[b];
    float* rois_out = out + (size_t)b * TROIS * 4;
    float* cls_out  = out + OFF_CLS + (size_t)b * TROIS;
    float* del_out  = out + OFF_DEL + (size_t)b * TROIS * 4;

    int t = threadIdx.x;
    if (t < PCAP) {
        float r0 = 0, r1 = 0, r2 = 0, r3 = 0;
        float c = 0, d0 = 0, d1 = 0, d2 = 0, d3 = 0;
        int ga = 0;
        if (t < np) {
            int n = d_pos_idx[b][t];
            const float* pp = props + ((size_t)b * NP + n) * 4;
            r0 = pp[0]; r1 = pp[1]; r2 = pp[2]; r3 = pp[3];
            float a1 = box_area(r0, r1, r2, r3);
            float best = -2.0f;
            for (int g = 0; g < NG; g++) {
                float v = s_ok[g] ? iou_pair(r0, r1, r2, r3, a1,
                                             s_g[g][0], s_g[g][1], s_g[g][2], s_g[g][3],
                                             s_area[g])
                                  : -1.0f;
                if (v > best) { best = v; ga = g; }
            }
            float gy1 = s_g[ga][0], gx1 = s_g[ga][1], gy2 = s_g[ga][2], gx2 = s_g[ga][3];
            float h  = __fsub_rn(r2, r0);
            float w  = __fsub_rn(r3, r1);
            float gh = __fsub_rn(gy2, gy1);
            float gw = __fsub_rn(gx2, gx1);
            float cy  = __fadd_rn(r0,  __fmul_rn(0.5f, h));
            float cx  = __fadd_rn(r1,  __fmul_rn(0.5f, w));
            float gcy = __fadd_rn(gy1, __fmul_rn(0.5f, gh));
            float gcx = __fadd_rn(gx1, __fmul_rn(0.5f, gw));
            d0 = __fdiv_rn(__fdiv_rn(__fsub_rn(gcy, cy), h), 0.1f);
            d1 = __fdiv_rn(__fdiv_rn(__fsub_rn(gcx, cx), w), 0.1f);
            d2 = __fdiv_rn((float)log((double)__fdiv_rn(gh, h)), 0.2f);
            d3 = __fdiv_rn((float)log((double)__fdiv_rn(gw, w)), 0.2f);
            c = (float)s_cls[ga];
        }
        d_gt_assign[b][t] = ga;
        d_pos_roi[b][t][0] = r0; d_pos_roi[b][t][1] = r1;
        d_pos_roi[b][t][2] = r2; d_pos_roi[b][t][3] = r3;
        rois_out[t * 4 + 0] = r0; rois_out[t * 4 + 1] = r1;
        rois_out[t * 4 + 2] = r2; rois_out[t * 4 + 3] = r3;
        cls_out[t] = c;
        del_out[t * 4 + 0] = d0; del_out[t * 4 + 1] = d1;
        del_out[t * 4 + 2] = d2; del_out[t * 4 + 3] = d3;
    } else if (t < TROIS) {
        int j = t - PCAP;
        float r0 = 0, r1 = 0, r2 = 0, r3 = 0;
        if (j < nn) {
            int n = d_neg_idx[b][j];
            const float* pp = props + ((size_t)b * NP + n) * 4;
            r0 = pp[0]; r1 = pp[1]; r2 = pp[2]; r3 = pp[3];
        }
        rois_out[t * 4 + 0] = r0; rois_out[t * 4 + 1] = r1;
        rois_out[t * 4 + 2] = r2; rois_out[t * 4 + 3] = r3;
        cls_out[t] = 0.0f;
        del_out[t * 4 + 0] = 0.0f; del_out[t * 4 + 1] = 0.0f;
        del_out[t * 4 + 2] = 0.0f; del_out[t * 4 + 3] = 0.0f;
    }
}

// ---------------------------------------------------------------------------
// Kernel D: mask targets. One block per (image, roi-slot); 1 pixel per thread
// (784 threads = 24.5 warps -> high MLP per SM for the 4 scattered gathers).
// ---------------------------------------------------------------------------
__device__ __forceinline__ float load_mask_val(const void* masks, int kind, size_t idx) {
    if (kind == 0) return (float)__ldg((const unsigned char*)masks + idx);
    if (kind == 1) return (float)__ldg((const int*)masks + idx);
    return __ldg((const float*)masks + idx);
}

__global__ void __launch_bounds__(MPIX) k_masks(const void* __restrict__ masks,
                                                float* __restrict__ out) {
    int slot = blockIdx.x % TROIS;
    int b    = blockIdx.x / TROIS;
    float* mout = out + OFF_MASK + ((size_t)(b * TROIS + slot)) * MPIX;
    int p = threadIdx.x;            // 0..783

    int np = d_num_pos[b];
    if (slot >= np || slot >= PCAP) {
        mout[p] = 0.0f;
        return;
    }
    int kind = d_mask_kind;
    float y1 = d_pos_roi[b][slot][0];
    float x1 = d_pos_roi[b][slot][1];
    float y2 = d_pos_roi[b][slot][2];
    float x2 = d_pos_roi[b][slot][3];
    int g = d_gt_assign[b][slot];
    float dy = __fsub_rn(y2, y1);
    float dx = __fsub_rn(x2, x1);

    int i = p / MS2;
    int j = p % MS2;
    // ys = (y1 + (y2-y1)*i/27) * 1023  — exact jnp op order, IEEE rn
    float ys = __fmul_rn(__fadd_rn(y1, __fdiv_rn(__fmul_rn(dy, (float)i), 27.0f)), 1023.0f);
    float xs = __fmul_rn(__fadd_rn(x1, __fdiv_rn(__fmul_rn(dx, (float)j), 27.0f)), 1023.0f);

    float y0f = fminf(fmaxf(floorf(ys), 0.0f), 1023.0f);
    float x0f = fminf(fmaxf(floorf(xs), 0.0f), 1023.0f);
    int y0 = (int)y0f;
    int x0 = (int)x0f;
    int y1i = (int)fminf(__fadd_rn(y0f, 1.0f), 1023.0f);
    int x1i = (int)fminf(__fadd_rn(x0f, 1.0f), 1023.0f);
    float wy = __fsub_rn(ys, y0f);
    float wx = __fsub_rn(xs, x0f);
    float oy = __fsub_rn(1.0f, wy);
    float ox = __fsub_rn(1.0f, wx);

    size_t base_b = (size_t)b * MH;
    size_t row0 = (base_b + (size_t)y0)  * MW;
    size_t row1 = (base_b + (size_t)y1i) * MW;
    float m00 = load_mask_val(masks, kind, (row0 + x0)  * NG + g);
    float m01 = load_mask_val(masks, kind, (row0 + x1i) * NG + g);
    float m10 = load_mask_val(masks, kind, (row1 + x0)  * NG + g);
    float m11 = load_mask_val(masks, kind, (row1 + x1i) * NG + g);

    float t0 = __fmul_rn(__fmul_rn(m00, oy), ox);
    float t1 = __fmul_rn(__fmul_rn(m01, oy), wx);
    float t2 = __fmul_rn(__fmul_rn(m10, wy), ox);
    float t3 = __fmul_rn(__fmul_rn(m11, wy), wx);
    float val = __fadd_rn(__fadd_rn(__fadd_rn(t0, t1), t2), t3);
    mout[p] = rintf(val);   // round-half-even, matches jnp.round
}

extern "C" void kernel_launch(void* const* d_in, const int* in_sizes, int n_in,
                              void* d_out, int out_size) {
    const float* props = (const float*)d_in[0];
    const int*   gtc   = (const int*)d_in[1];
    const float* gtb   = (const float*)d_in[2];
    const void*  masks = d_in[3];
    float* out = (float*)d_out;

    k_detect_kind<<<1, 1024>>>((const unsigned int*)masks);   // probes 1024 words
    k_flags_select<<<BB, 256>>>(props, gtc, gtb);
    k_outputs<<<BB, 256>>>(props, gtc, gtb, out);
    k_masks<<<BB * TROIS, MPIX>>>(masks, out);
}

// round 8
// speedup vs baseline: 7.3640x; 4.3759x over previous
#include <cuda_runtime.h>
#include <cstdint>

// Problem constants (fixed by setup_inputs)
#define BB    4
#define NP    2000
#define NG    100
#define MH    1024
#define MW    1024
#define PCAP  66
#define NCAP  134
#define TROIS 200
#define MS1   28
#define MS2   28
#define MPIX  (MS1*MS2)

#define CHUNKS   8            // flag blocks per image
#define CHUNK_SZ (NP/CHUNKS)  // 250 proposals per block
#define SEG      200          // selection segments
#define SEG_SZ   (NP/SEG)     // 10 proposals per segment

// Output layout (flattened tuple, all float32)
#define OFF_CLS   (BB*TROIS*4)
#define OFF_DEL   (BB*TROIS*4 + BB*TROIS)
#define OFF_MASK  (BB*TROIS*4 + BB*TROIS + BB*TROIS*4)

// Inter-kernel scratch
__device__ int           d_mask_kind;          // 0=uint8, 1=int32, 2=float32
__device__ unsigned char d_flag[BB][NP];       // 0 none, 1 pos, 2 neg
__device__ int           d_num_pos[BB];
__device__ int           d_gt_assign[BB][PCAP];
__device__ float         d_pos_roi[BB][PCAP][4];

// IEEE-exact IoU matching XLA op order (immune to --use_fast_math).
__device__ __forceinline__ float iou_pair(float py1,float px1,float py2,float px2,float a1,
                                          float gy1,float gx1,float gy2,float gx2,float a2){
    float y1 = fmaxf(py1, gy1);
    float x1 = fmaxf(px1, gx1);
    float y2 = fminf(py2, gy2);
    float x2 = fminf(px2, gx2);
    float dy = fmaxf(__fsub_rn(y2, y1), 0.0f);
    float dx = fmaxf(__fsub_rn(x2, x1), 0.0f);
    float inter = __fmul_rn(dy, dx);
    float uni = __fsub_rn(__fadd_rn(a1, a2), inter);
    return __fdiv_rn(inter, uni > 0.0f ? uni : 1.0f);
}

__device__ __forceinline__ float box_area(float y1, float x1, float y2, float x2) {
    return __fmul_rn(__fsub_rn(y2, y1), __fsub_rn(x2, x1));
}

// ---------------------------------------------------------------------------
// Kernel 1: flags (blocks 0..31: image b=blk/8, chunk blk%8, 1 proposal/thread)
//           + dtype probe (block 32).
// ---------------------------------------------------------------------------
__global__ void k_flags(const float* __restrict__ props,
                        const int*   __restrict__ gtc,
                        const float* __restrict__ gtb,
                        const unsigned int* __restrict__ mask_words) {
    if (blockIdx.x == BB * CHUNKS) {
        // dtype probe: 256 threads x 4 words = 1024 words
        __shared__ int s_flags;
        if (threadIdx.x == 0) s_flags = 0;
        __syncthreads();
        int f = 0;
        #pragma unroll
        for (int k = 0; k < 4; k++) {
            unsigned int w = mask_words[threadIdx.x + k * 256];
            if (w == 0x3F800000u) f |= 1;
            else if (w != 0u && w != 1u) f |= 2;
        }
        for (int o = 16; o > 0; o >>= 1) f |= __shfl_xor_sync(0xFFFFFFFFu, f, o);
        if ((threadIdx.x & 31) == 0 && f) atomicOr(&s_flags, f);
        __syncthreads();
        if (threadIdx.x == 0) {
            int fl = s_flags;
            d_mask_kind = (fl & 1) ? 2 : ((fl & 2) ? 0 : 1);
        }
        return;
    }

    int b     = blockIdx.x / CHUNKS;
    int chunk = blockIdx.x % CHUNKS;
    __shared__ float s_g[NG][4];
    __shared__ float s_area[NG];
    __shared__ unsigned char s_ok[NG];
    __shared__ unsigned char s_crowd[NG];

    for (int g = threadIdx.x; g < NG; g += blockDim.x) {
        const float* gp = gtb + ((size_t)b * NG + g) * 4;
        float y1 = gp[0], x1 = gp[1], y2 = gp[2], x2 = gp[3];
        s_g[g][0] = y1; s_g[g][1] = x1; s_g[g][2] = y2; s_g[g][3] = x2;
        bool valid = (y1 != 0.0f) || (x1 != 0.0f) || (y2 != 0.0f) || (x2 != 0.0f);
        int cls = gtc[(size_t)b * NG + g];
        s_ok[g]    = (valid && cls > 0) ? 1 : 0;
        s_crowd[g] = (valid && cls < 0) ? 1 : 0;
        s_area[g]  = box_area(y1, x1, y2, x2);
    }
    __syncthreads();

    int t = threadIdx.x;
    if (t < CHUNK_SZ) {
        int n = chunk * CHUNK_SZ + t;
        const float* pp = props + ((size_t)b * NP + n) * 4;
        float py1 = pp[0], px1 = pp[1], py2 = pp[2], px2 = pp[3];
        bool pv = (py1 != 0.0f) || (px1 != 0.0f) || (py2 != 0.0f) || (px2 != 0.0f);
        float a1 = box_area(py1, px1, py2, px2);
        float max_ok = -1.0f, max_crowd = -1.0f;
        for (int g = 0; g < NG; g++) {
            if (!(s_ok[g] | s_crowd[g])) continue;
            float v = iou_pair(py1, px1, py2, px2, a1,
                               s_g[g][0], s_g[g][1], s_g[g][2], s_g[g][3], s_area[g]);
            if (s_ok[g])    max_ok    = fmaxf(max_ok, v);
            if (s_crowd[g]) max_crowd = fmaxf(max_crowd, v);
        }
        unsigned char f = 0;
        if (pv) {
            if (max_ok >= 0.5f) f = 1;
            else if (max_crowd < 0.001f) f = 2;
        }
        d_flag[b][n] = f;
    }
}

// ---------------------------------------------------------------------------
// Kernel 2: per-image selection (parallel segment compaction) + all non-mask
// outputs (rois/class/deltas) + scratch for the mask kernel.
// ---------------------------------------------------------------------------
__global__ void k_select_outputs(const float* __restrict__ props,
                                 const int*   __restrict__ gtc,
                                 const float* __restrict__ gtb,
                                 float* __restrict__ out) {
    int b = blockIdx.x;
    __shared__ float s_g[NG][4];
    __shared__ float s_area[NG];
    __shared__ int   s_cls[NG];
    __shared__ unsigned char s_ok[NG];
    __shared__ unsigned char s_flag[NP];
    __shared__ short s_poff[SEG];
    __shared__ short s_noff[SEG];
    __shared__ int   s_np, s_nn;
    __shared__ short s_pos_idx[PCAP];
    __shared__ short s_neg_idx[NCAP];

    for (int g = threadIdx.x; g < NG; g += blockDim.x) {
        const float* gp = gtb + ((size_t)b * NG + g) * 4;
        float y1 = gp[0], x1 = gp[1], y2 = gp[2], x2 = gp[3];
        s_g[g][0] = y1; s_g[g][1] = x1; s_g[g][2] = y2; s_g[g][3] = x2;
        bool valid = (y1 != 0.0f) || (x1 != 0.0f) || (y2 != 0.0f) || (x2 != 0.0f);
        int cls = gtc[(size_t)b * NG + g];
        s_cls[g]  = cls;
        s_ok[g]   = (valid && cls > 0) ? 1 : 0;
        s_area[g] = box_area(y1, x1, y2, x2);
    }
    for (int n = threadIdx.x; n < NP; n += blockDim.x)
        s_flag[n] = d_flag[b][n];
    __syncthreads();

    int t = threadIdx.x;
    // Phase 1: per-segment pos/neg counts
    if (t < SEG) {
        int pc = 0, nc = 0;
        #pragma unroll
        for (int k = 0; k < SEG_SZ; k++) {
            unsigned char f = s_flag[t * SEG_SZ + k];
            pc += (f == 1);
            nc += (f == 2);
        }
        s_poff[t] = (short)pc;
        s_noff[t] = (short)nc;
    }
    __syncthreads();
    // Phase 2: exclusive prefix (thread 0, 200 iters — trivial)
    if (t == 0) {
        int rp = 0, rn = 0;
        for (int s = 0; s < SEG; s++) {
            int c = s_poff[s]; s_poff[s] = (short)rp; rp += c;
            c = s_noff[s];     s_noff[s] = (short)rn; rn += c;
        }
        int np = rp < PCAP ? rp : PCAP;
        int nn = rn < NCAP ? rn : NCAP;
        // XLA lowers x/0.33f to x * rn(1/0.33f): 66*3.03030300140381f = 200.0
        float recip = __fdiv_rn(1.0f, 0.33f);
        int neg_target = (int)__fmul_rn((float)np, recip) - np;
        if (neg_target < 0) neg_target = 0;
        s_np = np;
        s_nn = (nn < neg_target) ? nn : neg_target;
        d_num_pos[b] = np;
    }
    __syncthreads();
    // Phase 3: segments emit ordered indices at their exclusive offsets
    if (t < SEG) {
        int rp = s_poff[t], rn = s_noff[t];
        #pragma unroll
        for (int k = 0; k < SEG_SZ; k++) {
            int n = t * SEG_SZ + k;
            unsigned char f = s_flag[n];
            if (f == 1) { if (rp < PCAP) s_pos_idx[rp] = (short)n; rp++; }
            else if (f == 2) { if (rn < NCAP) s_neg_idx[rn] = (short)n; rn++; }
        }
    }
    __syncthreads();

    int np = s_np;
    int nn = s_nn;
    float* rois_out = out + (size_t)b * TROIS * 4;
    float* cls_out  = out + OFF_CLS + (size_t)b * TROIS;
    float* del_out  = out + OFF_DEL + (size_t)b * TROIS * 4;

    if (t < PCAP) {
        float r0 = 0, r1 = 0, r2 = 0, r3 = 0;
        float c = 0, d0 = 0, d1 = 0, d2 = 0, d3 = 0;
        int ga = 0;
        if (t < np) {
            int n = s_pos_idx[t];
            const float* pp = props + ((size_t)b * NP + n) * 4;
            r0 = pp[0]; r1 = pp[1]; r2 = pp[2]; r3 = pp[3];
            float a1 = box_area(r0, r1, r2, r3);
            float best = -2.0f;
            for (int g = 0; g < NG; g++) {
                float v = s_ok[g] ? iou_pair(r0, r1, r2, r3, a1,
                                             s_g[g][0], s_g[g][1], s_g[g][2], s_g[g][3],
                                             s_area[g])
                                  : -1.0f;
                if (v > best) { best = v; ga = g; }
            }
            float gy1 = s_g[ga][0], gx1 = s_g[ga][1], gy2 = s_g[ga][2], gx2 = s_g[ga][3];
            float h  = __fsub_rn(r2, r0);
            float w  = __fsub_rn(r3, r1);
            float gh = __fsub_rn(gy2, gy1);
            float gw = __fsub_rn(gx2, gx1);
            float cy  = __fadd_rn(r0,  __fmul_rn(0.5f, h));
            float cx  = __fadd_rn(r1,  __fmul_rn(0.5f, w));
            float gcy = __fadd_rn(gy1, __fmul_rn(0.5f, gh));
            float gcx = __fadd_rn(gx1, __fmul_rn(0.5f, gw));
            d0 = __fdiv_rn(__fdiv_rn(__fsub_rn(gcy, cy), h), 0.1f);
            d1 = __fdiv_rn(__fdiv_rn(__fsub_rn(gcx, cx), w), 0.1f);
            d2 = __fdiv_rn((float)log((double)__fdiv_rn(gh, h)), 0.2f);
            d3 = __fdiv_rn((float)log((double)__fdiv_rn(gw, w)), 0.2f);
            c = (float)s_cls[ga];
        }
        d_gt_assign[b][t] = ga;
        d_pos_roi[b][t][0] = r0; d_pos_roi[b][t][1] = r1;
        d_pos_roi[b][t][2] = r2; d_pos_roi[b][t][3] = r3;
        rois_out[t * 4 + 0] = r0; rois_out[t * 4 + 1] = r1;
        rois_out[t * 4 + 2] = r2; rois_out[t * 4 + 3] = r3;
        cls_out[t] = c;
        del_out[t * 4 + 0] = d0; del_out[t * 4 + 1] = d1;
        del_out[t * 4 + 2] = d2; del_out[t * 4 + 3] = d3;
    } else if (t < TROIS) {
        int j = t - PCAP;
        float r0 = 0, r1 = 0, r2 = 0, r3 = 0;
        if (j < nn) {
            int n = s_neg_idx[j];
            const float* pp = props + ((size_t)b * NP + n) * 4;
            r0 = pp[0]; r1 = pp[1]; r2 = pp[2]; r3 = pp[3];
        }
        rois_out[t * 4 + 0] = r0; rois_out[t * 4 + 1] = r1;
        rois_out[t * 4 + 2] = r2; rois_out[t * 4 + 3] = r3;
        cls_out[t] = 0.0f;
        del_out[t * 4 + 0] = 0.0f; del_out[t * 4 + 1] = 0.0f;
        del_out[t * 4 + 2] = 0.0f; del_out[t * 4 + 3] = 0.0f;
    }
}

// ---------------------------------------------------------------------------
// Kernel 3: mask targets. One block per (image, roi-slot); 1 pixel/thread.
// ---------------------------------------------------------------------------
__device__ __forceinline__ float load_mask_val(const void* masks, int kind, size_t idx) {
    if (kind == 0) return (float)__ldg((const unsigned char*)masks + idx);
    if (kind == 1) return (float)__ldg((const int*)masks + idx);
    return __ldg((const float*)masks + idx);
}

__global__ void __launch_bounds__(MPIX) k_masks(const void* __restrict__ masks,
                                                float* __restrict__ out) {
    int slot = blockIdx.x % TROIS;
    int b    = blockIdx.x / TROIS;
    float* mout = out + OFF_MASK + ((size_t)(b * TROIS + slot)) * MPIX;
    int p = threadIdx.x;            // 0..783

    int np = d_num_pos[b];
    if (slot >= np || slot >= PCAP) {
        mout[p] = 0.0f;
        return;
    }
    int kind = d_mask_kind;
    float y1 = d_pos_roi[b][slot][0];
    float x1 = d_pos_roi[b][slot][1];
    float y2 = d_pos_roi[b][slot][2];
    float x2 = d_pos_roi[b][slot][3];
    int g = d_gt_assign[b][slot];
    float dy = __fsub_rn(y2, y1);
    float dx = __fsub_rn(x2, x1);

    int i = p / MS2;
    int j = p % MS2;
    // ys = (y1 + (y2-y1)*i/27) * 1023  — exact jnp op order, IEEE rn
    float ys = __fmul_rn(__fadd_rn(y1, __fdiv_rn(__fmul_rn(dy, (float)i), 27.0f)), 1023.0f);
    float xs = __fmul_rn(__fadd_rn(x1, __fdiv_rn(__fmul_rn(dx, (float)j), 27.0f)), 1023.0f);

    float y0f = fminf(fmaxf(floorf(ys), 0.0f), 1023.0f);
    float x0f = fminf(fmaxf(floorf(xs), 0.0f), 1023.0f);
    int y0 = (int)y0f;
    int x0 = (int)x0f;
    int y1i = (int)fminf(__fadd_rn(y0f, 1.0f), 1023.0f);
    int x1i = (int)fminf(__fadd_rn(x0f, 1.0f), 1023.0f);
    float wy = __fsub_rn(ys, y0f);
    float wx = __fsub_rn(xs, x0f);
    float oy = __fsub_rn(1.0f, wy);
    float ox = __fsub_rn(1.0f, wx);

    size_t base_b = (size_t)b * MH;
    size_t row0 = (base_b + (size_t)y0)  * MW;
    size_t row1 = (base_b + (size_t)y1i) * MW;
    float m00 = load_mask_val(masks, kind, (row0 + x0)  * NG + g);
    float m01 = load_mask_val(masks, kind, (row0 + x1i) * NG + g);
    float m10 = load_mask_val(masks, kind, (row1 + x0)  * NG + g);
    float m11 = load_mask_val(masks, kind, (row1 + x1i) * NG + g);

    float t0 = __fmul_rn(__fmul_rn(m00, oy), ox);
    float t1 = __fmul_rn(__fmul_rn(m01, oy), wx);
    float t2 = __fmul_rn(__fmul_rn(m10, wy), ox);
    float t3 = __fmul_rn(__fmul_rn(m11, wy), wx);
    float val = __fadd_rn(__fadd_rn(__fadd_rn(t0, t1), t2), t3);
    mout[p] = rintf(val);   // round-half-even, matches jnp.round
}

extern "C" void kernel_launch(void* const* d_in, const int* in_sizes, int n_in,
                              void* d_out, int out_size) {
    const float* props = (const float*)d_in[0];
    const int*   gtc   = (const int*)d_in[1];
    const float* gtb   = (const float*)d_in[2];
    const void*  masks = d_in[3];
    float* out = (float*)d_out;

    k_flags<<<BB * CHUNKS + 1, 256>>>(props, gtc, gtb, (const unsigned int*)masks);
    k_select_outputs<<<BB, 256>>>(props, gtc, gtb, out);
    k_masks<<<BB * TROIS, MPIX>>>(masks, out);
}

// round 10
// speedup vs baseline: 10.9302x; 1.4843x over previous
#include <cuda_runtime.h>
#include <cstdint>

// Problem constants (fixed by setup_inputs)
#define BB    4
#define NP    2000
#define NG    100
#define MH    1024
#define MW    1024
#define PCAP  66
#define NCAP  134
#define TROIS 200
#define MS1   28
#define MS2   28
#define MPIX  (MS1*MS2)

#define CHUNKS   16           // flag blocks per image
#define CHUNK_SZ (NP/CHUNKS)  // 125 proposals per block
#define SEG      200          // selection segments
#define SEG_SZ   (NP/SEG)     // 10 proposals per segment

// Output layout (flattened tuple, all float32)
#define OFF_CLS   (BB*TROIS*4)
#define OFF_DEL   (BB*TROIS*4 + BB*TROIS)
#define OFF_MASK  (BB*TROIS*4 + BB*TROIS + BB*TROIS*4)

// Inter-kernel scratch
__device__ int           d_mask_kind;          // 0=uint8, 1=int32, 2=float32
__device__ unsigned char d_flag[BB][NP];       // 0 none, 1 pos, 2 neg
__device__ int           d_num_pos[BB];
__device__ int           d_gt_assign[BB][PCAP];
__device__ float         d_pos_roi[BB][PCAP][4];

// IEEE-exact IoU matching XLA op order (immune to --use_fast_math).
__device__ __forceinline__ float iou_pair(float py1,float px1,float py2,float px2,float a1,
                                          float gy1,float gx1,float gy2,float gx2,float a2){
    float y1 = fmaxf(py1, gy1);
    float x1 = fmaxf(px1, gx1);
    float y2 = fminf(py2, gy2);
    float x2 = fminf(px2, gx2);
    float dy = fmaxf(__fsub_rn(y2, y1), 0.0f);
    float dx = fmaxf(__fsub_rn(x2, x1), 0.0f);
    float inter = __fmul_rn(dy, dx);
    float uni = __fsub_rn(__fadd_rn(a1, a2), inter);
    return __fdiv_rn(inter, uni > 0.0f ? uni : 1.0f);
}

__device__ __forceinline__ float box_area(float y1, float x1, float y2, float x2) {
    return __fmul_rn(__fsub_rn(y2, y1), __fsub_rn(x2, x1));
}

// ---------------------------------------------------------------------------
// Kernel 1: flags. Division-free predicates with exact-division fallback in a
// narrow band around the thresholds (rn division is monotone; 0.5*u is exact,
// so rn(i/u)>=0.5 <=> i>=0.5u except within half-ulp below the boundary).
// blocks 0..BB*CHUNKS-1: proposal flags.  block BB*CHUNKS: dtype probe.
// ---------------------------------------------------------------------------
__global__ void k_flags(const float* __restrict__ props,
                        const int*   __restrict__ gtc,
                        const float* __restrict__ gtb,
                        const unsigned int* __restrict__ mask_words) {
    if (blockIdx.x == BB * CHUNKS) {
        __shared__ int s_flags;
        if (threadIdx.x == 0) s_flags = 0;
        __syncthreads();
        int f = 0;
        #pragma unroll
        for (int k = 0; k < 8; k++) {
            unsigned int w = mask_words[threadIdx.x + k * 128];
            if (w == 0x3F800000u) f |= 1;
            else if (w != 0u && w != 1u) f |= 2;
        }
        for (int o = 16; o > 0; o >>= 1) f |= __shfl_xor_sync(0xFFFFFFFFu, f, o);
        if ((threadIdx.x & 31) == 0 && f) atomicOr(&s_flags, f);
        __syncthreads();
        if (threadIdx.x == 0) {
            int fl = s_flags;
            d_mask_kind = (fl & 1) ? 2 : ((fl & 2) ? 0 : 1);
        }
        return;
    }

    int b     = blockIdx.x / CHUNKS;
    int chunk = blockIdx.x % CHUNKS;
    // Compacted valid-GT lists (SoA, broadcast-friendly)
    __shared__ float s_gy1[NG], s_gx1[NG], s_gy2[NG], s_gx2[NG], s_ga2[NG];
    __shared__ float s_cy1[NG], s_cx1[NG], s_cy2[NG], s_cx2[NG], s_ca2[NG];
    __shared__ int   s_nok, s_ncrowd;

    if (threadIdx.x == 0) { s_nok = 0; s_ncrowd = 0; }
    __syncthreads();
    for (int g = threadIdx.x; g < NG; g += blockDim.x) {
        const float* gp = gtb + ((size_t)b * NG + g) * 4;
        float y1 = gp[0], x1 = gp[1], y2 = gp[2], x2 = gp[3];
        bool valid = (y1 != 0.0f) || (x1 != 0.0f) || (y2 != 0.0f) || (x2 != 0.0f);
        int cls = gtc[(size_t)b * NG + g];
        if (valid && cls > 0) {
            int s = atomicAdd(&s_nok, 1);
            s_gy1[s] = y1; s_gx1[s] = x1; s_gy2[s] = y2; s_gx2[s] = x2;
            s_ga2[s] = box_area(y1, x1, y2, x2);
        } else if (valid && cls < 0) {
            int s = atomicAdd(&s_ncrowd, 1);
            s_cy1[s] = y1; s_cx1[s] = x1; s_cy2[s] = y2; s_cx2[s] = x2;
            s_ca2[s] = box_area(y1, x1, y2, x2);
        }
    }
    __syncthreads();

    int t = threadIdx.x;
    if (t < CHUNK_SZ) {
        int n = chunk * CHUNK_SZ + t;
        const float* pp = props + ((size_t)b * NP + n) * 4;
        float py1 = pp[0], px1 = pp[1], py2 = pp[2], px2 = pp[3];
        bool pv = (py1 != 0.0f) || (px1 != 0.0f) || (py2 != 0.0f) || (px2 != 0.0f);
        float a1 = box_area(py1, px1, py2, px2);

        bool pos = false;
        int nok = s_nok;
        for (int s = 0; s < nok; s++) {
            float y1 = fmaxf(py1, s_gy1[s]);
            float x1 = fmaxf(px1, s_gx1[s]);
            float y2 = fminf(py2, s_gy2[s]);
            float x2 = fminf(px2, s_gx2[s]);
            float inter = __fmul_rn(fmaxf(__fsub_rn(y2, y1), 0.0f),
                                    fmaxf(__fsub_rn(x2, x1), 0.0f));
            float uni = __fsub_rn(__fadd_rn(a1, s_ga2[s]), inter);
            float denom = uni > 0.0f ? uni : 1.0f;
            float half_u = __fmul_rn(0.5f, denom);     // exact
            if (inter >= half_u) { pos = true; }
            else if (inter >= __fmul_rn(half_u, 0.999999f)) {
                // half-ulp band: decide with the exact rn division
                if (__fdiv_rn(inter, denom) >= 0.5f) pos = true;
            }
        }
        bool crowd_hit = false;
        int ncr = s_ncrowd;
        for (int s = 0; s < ncr; s++) {       // (empty for this dataset)
            float y1 = fmaxf(py1, s_cy1[s]);
            float x1 = fmaxf(px1, s_cx1[s]);
            float y2 = fminf(py2, s_cy2[s]);
            float x2 = fminf(px2, s_cx2[s]);
            float inter = __fmul_rn(fmaxf(__fsub_rn(y2, y1), 0.0f),
                                    fmaxf(__fsub_rn(x2, x1), 0.0f));
            float uni = __fsub_rn(__fadd_rn(a1, s_ca2[s]), inter);
            float denom = uni > 0.0f ? uni : 1.0f;
            if (inter >= __fmul_rn(denom, 0.001001f)) crowd_hit = true;
            else if (inter >= __fmul_rn(denom, 0.000999f)) {
                if (__fdiv_rn(inter, denom) >= 0.001f) crowd_hit = true;
            }
        }
        unsigned char f = 0;
        if (pv) {
            if (pos) f = 1;
            else if (!crowd_hit) f = 2;
        }
        d_flag[b][n] = f;
    }
}

// ---------------------------------------------------------------------------
// Kernel 2: per-image selection (parallel segment compaction) + rois/class/
// deltas; GT argmax parallelized 4-way per positive. Block = 288 threads.
// Phase 4 is executed by ALL threads (warp-uniform) so __shfl_down_sync's
// full mask is legal; out-of-range rois carry dummies.
// ---------------------------------------------------------------------------
__global__ void __launch_bounds__(288) k_select_outputs(
        const float* __restrict__ props,
        const int*   __restrict__ gtc,
        const float* __restrict__ gtb,
        float* __restrict__ out) {
    int b = blockIdx.x;
    __shared__ float s_g[NG][4];
    __shared__ float s_area[NG];
    __shared__ int   s_cls[NG];
    __shared__ unsigned char s_ok[NG];
    __shared__ unsigned char s_flag[NP];
    __shared__ short s_poff[SEG];
    __shared__ short s_noff[SEG];
    __shared__ int   s_np, s_nn;
    __shared__ short s_pos_idx[PCAP];
    __shared__ short s_neg_idx[NCAP];
    __shared__ int   s_ga[PCAP];

    for (int g = threadIdx.x; g < NG; g += blockDim.x) {
        const float* gp = gtb + ((size_t)b * NG + g) * 4;
        float y1 = gp[0], x1 = gp[1], y2 = gp[2], x2 = gp[3];
        s_g[g][0] = y1; s_g[g][1] = x1; s_g[g][2] = y2; s_g[g][3] = x2;
        bool valid = (y1 != 0.0f) || (x1 != 0.0f) || (y2 != 0.0f) || (x2 != 0.0f);
        int cls = gtc[(size_t)b * NG + g];
        s_cls[g]  = cls;
        s_ok[g]   = (valid && cls > 0) ? 1 : 0;
        s_area[g] = box_area(y1, x1, y2, x2);
    }
    for (int n = threadIdx.x; n < NP; n += blockDim.x)
        s_flag[n] = d_flag[b][n];
    __syncthreads();

    int t = threadIdx.x;
    // Phase 1: per-segment pos/neg counts
    if (t < SEG) {
        int pc = 0, nc = 0;
        #pragma unroll
        for (int k = 0; k < SEG_SZ; k++) {
            unsigned char f = s_flag[t * SEG_SZ + k];
            pc += (f == 1);
            nc += (f == 2);
        }
        s_poff[t] = (short)pc;
        s_noff[t] = (short)nc;
    }
    __syncthreads();
    // Phase 2: exclusive prefix (thread 0)
    if (t == 0) {
        int rp = 0, rn = 0;
        for (int s = 0; s < SEG; s++) {
            int c = s_poff[s]; s_poff[s] = (short)rp; rp += c;
            c = s_noff[s];     s_noff[s] = (short)rn; rn += c;
        }
        int np = rp < PCAP ? rp : PCAP;
        int nn = rn < NCAP ? rn : NCAP;
        // XLA lowers x/0.33f to x * rn(1/0.33f): 66*3.03030300140381f = 200.0
        float recip = __fdiv_rn(1.0f, 0.33f);
        int neg_target = (int)__fmul_rn((float)np, recip) - np;
        if (neg_target < 0) neg_target = 0;
        s_np = np;
        s_nn = (nn < neg_target) ? nn : neg_target;
        d_num_pos[b] = np;
    }
    __syncthreads();
    // Phase 3: segments emit ordered indices at their exclusive offsets
    if (t < SEG) {
        int rp = s_poff[t], rn = s_noff[t];
        #pragma unroll
        for (int k = 0; k < SEG_SZ; k++) {
            int n = t * SEG_SZ + k;
            unsigned char f = s_flag[n];
            if (f == 1) { if (rp < PCAP) s_pos_idx[rp] = (short)n; rp++; }
            else if (f == 2) { if (rn < NCAP) s_neg_idx[rn] = (short)n; rn++; }
        }
    }
    __syncthreads();

    int np = s_np;
    int nn = s_nn;

    // Phase 4: GT argmax, 4 threads per positive ROI (25 GTs each).
    // ALL 288 threads execute (roi up to 71); roi>=np contribute dummies.
    {
        int roi  = t >> 2;
        int part = t & 3;
        float best_v = -2.0f;
        int   best_g = 0;
        if (roi < np) {
            int n = s_pos_idx[roi];
            const float* pp = props + ((size_t)b * NP + n) * 4;
            float r0 = pp[0], r1 = pp[1], r2 = pp[2], r3 = pp[3];
            float a1 = box_area(r0, r1, r2, r3);
            int g0 = part * (NG / 4);
            for (int g = g0; g < g0 + NG / 4; g++) {
                float v = s_ok[g] ? iou_pair(r0, r1, r2, r3, a1,
                                             s_g[g][0], s_g[g][1], s_g[g][2], s_g[g][3],
                                             s_area[g])
                                  : -1.0f;
                if (v > best_v) { best_v = v; best_g = g; }
            }
        }
        // (v desc, g asc) reduce over the 4 partitions => first-max semantics
        #pragma unroll
        for (int o = 2; o > 0; o >>= 1) {
            float ov = __shfl_down_sync(0xFFFFFFFFu, best_v, o, 4);
            int   og = __shfl_down_sync(0xFFFFFFFFu, best_g, o, 4);
            if (ov > best_v || (ov == best_v && og < best_g)) { best_v = ov; best_g = og; }
        }
        if (part == 0 && roi < PCAP) s_ga[roi] = (roi < np) ? best_g : 0;
    }
    __syncthreads();

    float* rois_out = out + (size_t)b * TROIS * 4;
    float* cls_out  = out + OFF_CLS + (size_t)b * TROIS;
    float* del_out  = out + OFF_DEL + (size_t)b * TROIS * 4;

    if (t < PCAP) {
        float r0 = 0, r1 = 0, r2 = 0, r3 = 0;
        float c = 0, d0 = 0, d1 = 0, d2 = 0, d3 = 0;
        int ga = s_ga[t];
        if (t < np) {
            int n = s_pos_idx[t];
            const float* pp = props + ((size_t)b * NP + n) * 4;
            r0 = pp[0]; r1 = pp[1]; r2 = pp[2]; r3 = pp[3];
            float gy1 = s_g[ga][0], gx1 = s_g[ga][1], gy2 = s_g[ga][2], gx2 = s_g[ga][3];
            float h  = __fsub_rn(r2, r0);
            float w  = __fsub_rn(r3, r1);
            float gh = __fsub_rn(gy2, gy1);
            float gw = __fsub_rn(gx2, gx1);
            float cy  = __fadd_rn(r0,  __fmul_rn(0.5f, h));
            float cx  = __fadd_rn(r1,  __fmul_rn(0.5f, w));
            float gcy = __fadd_rn(gy1, __fmul_rn(0.5f, gh));
            float gcx = __fadd_rn(gx1, __fmul_rn(0.5f, gw));
            d0 = __fdiv_rn(__fdiv_rn(__fsub_rn(gcy, cy), h), 0.1f);
            d1 = __fdiv_rn(__fdiv_rn(__fsub_rn(gcx, cx), w), 0.1f);
            d2 = __fdiv_rn((float)log((double)__fdiv_rn(gh, h)), 0.2f);
            d3 = __fdiv_rn((float)log((double)__fdiv_rn(gw, w)), 0.2f);
            c = (float)s_cls[ga];
        }
        d_gt_assign[b][t] = ga;
        d_pos_roi[b][t][0] = r0; d_pos_roi[b][t][1] = r1;
        d_pos_roi[b][t][2] = r2; d_pos_roi[b][t][3] = r3;
        rois_out[t * 4 + 0] = r0; rois_out[t * 4 + 1] = r1;
        rois_out[t * 4 + 2] = r2; rois_out[t * 4 + 3] = r3;
        cls_out[t] = c;
        del_out[t * 4 + 0] = d0; del_out[t * 4 + 1] = d1;
        del_out[t * 4 + 2] = d2; del_out[t * 4 + 3] = d3;
    } else if (t < TROIS) {
        int j = t - PCAP;
        float r0 = 0, r1 = 0, r2 = 0, r3 = 0;
        if (j < nn) {
            int n = s_neg_idx[j];
            const float* pp = props + ((size_t)b * NP + n) * 4;
            r0 = pp[0]; r1 = pp[1]; r2 = pp[2]; r3 = pp[3];
        }
        rois_out[t * 4 + 0] = r0; rois_out[t * 4 + 1] = r1;
        rois_out[t * 4 + 2] = r2; rois_out[t * 4 + 3] = r3;
        cls_out[t] = 0.0f;
        del_out[t * 4 + 0] = 0.0f; del_out[t * 4 + 1] = 0.0f;
        del_out[t * 4 + 2] = 0.0f; del_out[t * 4 + 3] = 0.0f;
    }
}

// ---------------------------------------------------------------------------
// Kernel 3: mask targets. TWO blocks per (image, roi-slot), 392 threads each
// -> 5 blocks/SM (95% occ) for maximum scattered-load MLP.
// ---------------------------------------------------------------------------
#define MBLK 392
__device__ __forceinline__ float load_mask_val(const void* masks, int kind, size_t idx) {
    if (kind == 0) return (float)__ldg((const unsigned char*)masks + idx);
    if (kind == 1) return (float)__ldg((const int*)masks + idx);
    return __ldg((const float*)masks + idx);
}

__global__ void __launch_bounds__(MBLK) k_masks(const void* __restrict__ masks,
                                                float* __restrict__ out) {
    int part = blockIdx.x & 1;
    int sb   = blockIdx.x >> 1;
    int slot = sb % TROIS;
    int b    = sb / TROIS;
    int p    = part * MBLK + threadIdx.x;     // 0..783
    float* mout = out + OFF_MASK + ((size_t)(b * TROIS + slot)) * MPIX;

    int np = d_num_pos[b];
    if (slot >= np || slot >= PCAP) {
        mout[p] = 0.0f;
        return;
    }
    int kind = d_mask_kind;
    float y1 = d_pos_roi[b][slot][0];
    float x1 = d_pos_roi[b][slot][1];
    float y2 = d_pos_roi[b][slot][2];
    float x2 = d_pos_roi[b][slot][3];
    int g = d_gt_assign[b][slot];
    float dy = __fsub_rn(y2, y1);
    float dx = __fsub_rn(x2, x1);

    int i = p / MS2;
    int j = p % MS2;
    // ys = (y1 + (y2-y1)*i/27) * 1023  — exact jnp op order, IEEE rn
    float ys = __fmul_rn(__fadd_rn(y1, __fdiv_rn(__fmul_rn(dy, (float)i), 27.0f)), 1023.0f);
    float xs = __fmul_rn(__fadd_rn(x1, __fdiv_rn(__fmul_rn(dx, (float)j), 27.0f)), 1023.0f);

    float y0f = fminf(fmaxf(floorf(ys), 0.0f), 1023.0f);
    float x0f = fminf(fmaxf(floorf(xs), 0.0f), 1023.0f);
    int y0 = (int)y0f;
    int x0 = (int)x0f;
    int y1i = (int)fminf(__fadd_rn(y0f, 1.0f), 1023.0f);
    int x1i = (int)fminf(__fadd_rn(x0f, 1.0f), 1023.0f);
    float wy = __fsub_rn(ys, y0f);
    float wx = __fsub_rn(xs, x0f);
    float oy = __fsub_rn(1.0f, wy);
    float ox = __fsub_rn(1.0f, wx);

    size_t base_b = (size_t)b * MH;
    size_t row0 = (base_b + (size_t)y0)  * MW;
    size_t row1 = (base_b + (size_t)y1i) * MW;
    float m00 = load_mask_val(masks, kind, (row0 + x0)  * NG + g);
    float m01 = load_mask_val(masks, kind, (row0 + x1i) * NG + g);
    float m10 = load_mask_val(masks, kind, (row1 + x0)  * NG + g);
    float m11 = load_mask_val(masks, kind, (row1 + x1i) * NG + g);

    float t0 = __fmul_rn(__fmul_rn(m00, oy), ox);
    float t1 = __fmul_rn(__fmul_rn(m01, oy), wx);
    float t2 = __fmul_rn(__fmul_rn(m10, wy), ox);
    float t3 = __fmul_rn(__fmul_rn(m11, wy), wx);
    float val = __fadd_rn(__fadd_rn(__fadd_rn(t0, t1), t2), t3);
    mout[p] = rintf(val);   // round-half-even, matches jnp.round
}

extern "C" void kernel_launch(void* const* d_in, const int* in_sizes, int n_in,
                              void* d_out, int out_size) {
    const float* props = (const float*)d_in[0];
    const int*   gtc   = (const int*)d_in[1];
    const float* gtb   = (const float*)d_in[2];
    const void*  masks = d_in[3];
    float* out = (float*)d_out;

    k_flags<<<BB * CHUNKS + 1, 128>>>(props, gtc, gtb, (const unsigned int*)masks);
    k_select_outputs<<<BB, 288>>>(props, gtc, gtb, out);
    k_masks<<<BB * TROIS * 2, MBLK>>>(masks, out);
}

// round 12
// speedup vs baseline: 13.3227x; 1.2189x over previous
#include <cuda_runtime.h>
#include <cstdint>

// Problem constants (fixed by setup_inputs)
#define BB    4
#define NP    2000
#define NG    100
#define MH    1024
#define MW    1024
#define PCAP  66
#define NCAP  134
#define TROIS 200
#define MS1   28
#define MS2   28
#define MPIX  (MS1*MS2)

#define CHUNKS   16           // flag blocks per image
#define CHUNK_SZ (NP/CHUNKS)  // 125 proposals per block
#define FBLK     512          // 4 threads per proposal
#define SEG      200          // selection segments
#define SEG_SZ   (NP/SEG)     // 10 proposals per segment

// Output layout (flattened tuple, all float32)
#define OFF_CLS   (BB*TROIS*4)
#define OFF_DEL   (BB*TROIS*4 + BB*TROIS)
#define OFF_MASK  (BB*TROIS*4 + BB*TROIS + BB*TROIS*4)

// Inter-kernel scratch
__device__ int           d_mask_kind;          // 0=uint8, 1=int32, 2=float32
__device__ unsigned char d_flag[BB][NP];       // 0 none, 1 pos, 2 neg
__device__ int           d_num_pos[BB];
__device__ int           d_gt_assign[BB][PCAP];
__device__ float         d_pos_roi[BB][PCAP][4];

// IEEE-exact IoU matching XLA op order (immune to --use_fast_math).
__device__ __forceinline__ float iou_pair(float py1,float px1,float py2,float px2,float a1,
                                          float gy1,float gx1,float gy2,float gx2,float a2){
    float y1 = fmaxf(py1, gy1);
    float x1 = fmaxf(px1, gx1);
    float y2 = fminf(py2, gy2);
    float x2 = fminf(px2, gx2);
    float dy = fmaxf(__fsub_rn(y2, y1), 0.0f);
    float dx = fmaxf(__fsub_rn(x2, x1), 0.0f);
    float inter = __fmul_rn(dy, dx);
    float uni = __fsub_rn(__fadd_rn(a1, a2), inter);
    return __fdiv_rn(inter, uni > 0.0f ? uni : 1.0f);
}

__device__ __forceinline__ float box_area(float y1, float x1, float y2, float x2) {
    return __fmul_rn(__fsub_rn(y2, y1), __fsub_rn(x2, x1));
}

// ---------------------------------------------------------------------------
// Kernel 1: flags. 4 threads per proposal (GTs strided by 4), division-free
// predicates with exact-division fallback in a narrow band around thresholds
// (rn division is monotone; 0.5*u is exact). Predicates are ORs, so the 4-way
// split is order-independent and bitwise-safe.
// blocks 0..BB*CHUNKS-1: proposal flags.  block BB*CHUNKS: dtype probe.
// ---------------------------------------------------------------------------
__global__ void __launch_bounds__(FBLK) k_flags(
        const float* __restrict__ props,
        const int*   __restrict__ gtc,
        const float* __restrict__ gtb,
        const unsigned int* __restrict__ mask_words) {
    if (blockIdx.x == BB * CHUNKS) {
        __shared__ int s_flags;
        if (threadIdx.x == 0) s_flags = 0;
        __syncthreads();
        int f = 0;
        #pragma unroll
        for (int k = 0; k < 2; k++) {
            unsigned int w = mask_words[threadIdx.x + k * FBLK];
            if (w == 0x3F800000u) f |= 1;
            else if (w != 0u && w != 1u) f |= 2;
        }
        for (int o = 16; o > 0; o >>= 1) f |= __shfl_xor_sync(0xFFFFFFFFu, f, o);
        if ((threadIdx.x & 31) == 0 && f) atomicOr(&s_flags, f);
        __syncthreads();
        if (threadIdx.x == 0) {
            int fl = s_flags;
            d_mask_kind = (fl & 1) ? 2 : ((fl & 2) ? 0 : 1);
        }
        return;
    }

    int b     = blockIdx.x / CHUNKS;
    int chunk = blockIdx.x % CHUNKS;
    // Compacted valid-GT lists (SoA, broadcast-friendly)
    __shared__ float s_gy1[NG], s_gx1[NG], s_gy2[NG], s_gx2[NG], s_ga2[NG];
    __shared__ float s_cy1[NG], s_cx1[NG], s_cy2[NG], s_cx2[NG], s_ca2[NG];
    __shared__ int   s_nok, s_ncrowd;

    if (threadIdx.x == 0) { s_nok = 0; s_ncrowd = 0; }
    __syncthreads();
    if (threadIdx.x < NG) {
        int g = threadIdx.x;
        const float* gp = gtb + ((size_t)b * NG + g) * 4;
        float y1 = gp[0], x1 = gp[1], y2 = gp[2], x2 = gp[3];
        bool valid = (y1 != 0.0f) || (x1 != 0.0f) || (y2 != 0.0f) || (x2 != 0.0f);
        int cls = gtc[(size_t)b * NG + g];
        if (valid && cls > 0) {
            int s = atomicAdd(&s_nok, 1);
            s_gy1[s] = y1; s_gx1[s] = x1; s_gy2[s] = y2; s_gx2[s] = x2;
            s_ga2[s] = box_area(y1, x1, y2, x2);
        } else if (valid && cls < 0) {
            int s = atomicAdd(&s_ncrowd, 1);
            s_cy1[s] = y1; s_cx1[s] = x1; s_cy2[s] = y2; s_cx2[s] = x2;
            s_ca2[s] = box_area(y1, x1, y2, x2);
        }
    }
    __syncthreads();

    int t    = threadIdx.x;
    int idx  = t >> 2;        // proposal within chunk (0..127)
    int part = t & 3;
    bool active = idx < CHUNK_SZ;
    int n = chunk * CHUNK_SZ + idx;

    float py1 = 0, px1 = 0, py2 = 0, px2 = 0, a1 = 0;
    bool pv = false;
    if (active) {
        const float* pp = props + ((size_t)b * NP + n) * 4;
        py1 = pp[0]; px1 = pp[1]; py2 = pp[2]; px2 = pp[3];
        pv = (py1 != 0.0f) || (px1 != 0.0f) || (py2 != 0.0f) || (px2 != 0.0f);
        a1 = box_area(py1, px1, py2, px2);
    }

    int pos = 0, crowd_hit = 0;
    if (active && pv) {
        int nok = s_nok;
        for (int s = part; s < nok; s += 4) {
            float y1 = fmaxf(py1, s_gy1[s]);
            float x1 = fmaxf(px1, s_gx1[s]);
            float y2 = fminf(py2, s_gy2[s]);
            float x2 = fminf(px2, s_gx2[s]);
            float inter = __fmul_rn(fmaxf(__fsub_rn(y2, y1), 0.0f),
                                    fmaxf(__fsub_rn(x2, x1), 0.0f));
            float uni = __fsub_rn(__fadd_rn(a1, s_ga2[s]), inter);
            float denom = uni > 0.0f ? uni : 1.0f;
            float half_u = __fmul_rn(0.5f, denom);     // exact
            if (inter >= half_u) { pos = 1; }
            else if (inter >= __fmul_rn(half_u, 0.999999f)) {
                if (__fdiv_rn(inter, denom) >= 0.5f) pos = 1;   // half-ulp band
            }
        }
        int ncr = s_ncrowd;
        for (int s = part; s < ncr; s += 4) {   // (empty for this dataset)
            float y1 = fmaxf(py1, s_cy1[s]);
            float x1 = fmaxf(px1, s_cx1[s]);
            float y2 = fminf(py2, s_cy2[s]);
            float x2 = fminf(px2, s_cx2[s]);
            float inter = __fmul_rn(fmaxf(__fsub_rn(y2, y1), 0.0f),
                                    fmaxf(__fsub_rn(x2, x1), 0.0f));
            float uni = __fsub_rn(__fadd_rn(a1, s_ca2[s]), inter);
            float denom = uni > 0.0f ? uni : 1.0f;
            if (inter >= __fmul_rn(denom, 0.001001f)) crowd_hit = 1;
            else if (inter >= __fmul_rn(denom, 0.000999f)) {
                if (__fdiv_rn(inter, denom) >= 0.001f) crowd_hit = 1;
            }
        }
    }
    // OR-combine across the 4 partitions (warp-uniform shuffles)
    #pragma unroll
    for (int o = 2; o > 0; o >>= 1) {
        pos       |= __shfl_down_sync(0xFFFFFFFFu, pos, o, 4);
        crowd_hit |= __shfl_down_sync(0xFFFFFFFFu, crowd_hit, o, 4);
    }
    if (part == 0 && active) {
        unsigned char f = 0;
        if (pv) {
            if (pos) f = 1;
            else if (!crowd_hit) f = 2;
        }
        d_flag[b][n] = f;
    }
}

// ---------------------------------------------------------------------------
// Kernel 2: per-image selection (parallel segment compaction) + rois/class/
// deltas; GT argmax parallelized 4-way per positive. Block = 288 threads.
// Phase 4 executed by ALL threads (warp-uniform shuffles).
// ---------------------------------------------------------------------------
__global__ void __launch_bounds__(288) k_select_outputs(
        const float* __restrict__ props,
        const int*   __restrict__ gtc,
        const float* __restrict__ gtb,
        float* __restrict__ out) {
    int b = blockIdx.x;
    __shared__ float s_g[NG][4];
    __shared__ float s_area[NG];
    __shared__ int   s_cls[NG];
    __shared__ unsigned char s_ok[NG];
    __shared__ unsigned char s_flag[NP];
    __shared__ short s_poff[SEG];
    __shared__ short s_noff[SEG];
    __shared__ int   s_np, s_nn;
    __shared__ short s_pos_idx[PCAP];
    __shared__ short s_neg_idx[NCAP];
    __shared__ int   s_ga[PCAP];

    for (int g = threadIdx.x; g < NG; g += blockDim.x) {
        const float* gp = gtb + ((size_t)b * NG + g) * 4;
        float y1 = gp[0], x1 = gp[1], y2 = gp[2], x2 = gp[3];
        s_g[g][0] = y1; s_g[g][1] = x1; s_g[g][2] = y2; s_g[g][3] = x2;
        bool valid = (y1 != 0.0f) || (x1 != 0.0f) || (y2 != 0.0f) || (x2 != 0.0f);
        int cls = gtc[(size_t)b * NG + g];
        s_cls[g]  = cls;
        s_ok[g]   = (valid && cls > 0) ? 1 : 0;
        s_area[g] = box_area(y1, x1, y2, x2);
    }
    for (int n = threadIdx.x; n < NP; n += blockDim.x)
        s_flag[n] = d_flag[b][n];
    __syncthreads();

    int t = threadIdx.x;
    // Phase 1: per-segment pos/neg counts
    if (t < SEG) {
        int pc = 0, nc = 0;
        #pragma unroll
        for (int k = 0; k < SEG_SZ; k++) {
            unsigned char f = s_flag[t * SEG_SZ + k];
            pc += (f == 1);
            nc += (f == 2);
        }
        s_poff[t] = (short)pc;
        s_noff[t] = (short)nc;
    }
    __syncthreads();
    // Phase 2: exclusive prefix (thread 0)
    if (t == 0) {
        int rp = 0, rn = 0;
        for (int s = 0; s < SEG; s++) {
            int c = s_poff[s]; s_poff[s] = (short)rp; rp += c;
            c = s_noff[s];     s_noff[s] = (short)rn; rn += c;
        }
        int np = rp < PCAP ? rp : PCAP;
        int nn = rn < NCAP ? rn : NCAP;
        // XLA lowers x/0.33f to x * rn(1/0.33f): 66*3.03030300140381f = 200.0
        float recip = __fdiv_rn(1.0f, 0.33f);
        int neg_target = (int)__fmul_rn((float)np, recip) - np;
        if (neg_target < 0) neg_target = 0;
        s_np = np;
        s_nn = (nn < neg_target) ? nn : neg_target;
        d_num_pos[b] = np;
    }
    __syncthreads();
    // Phase 3: segments emit ordered indices at their exclusive offsets
    if (t < SEG) {
        int rp = s_poff[t], rn = s_noff[t];
        #pragma unroll
        for (int k = 0; k < SEG_SZ; k++) {
            int n = t * SEG_SZ + k;
            unsigned char f = s_flag[n];
            if (f == 1) { if (rp < PCAP) s_pos_idx[rp] = (short)n; rp++; }
            else if (f == 2) { if (rn < NCAP) s_neg_idx[rn] = (short)n; rn++; }
        }
    }
    __syncthreads();

    int np = s_np;
    int nn = s_nn;

    // Phase 4: GT argmax, 4 threads per positive ROI (25 GTs each).
    // ALL 288 threads execute; roi>=np contribute dummies.
    {
        int roi  = t >> 2;
        int part = t & 3;
        float best_v = -2.0f;
        int   best_g = 0;
        if (roi < np) {
            int n = s_pos_idx[roi];
            const float* pp = props + ((size_t)b * NP + n) * 4;
            float r0 = pp[0], r1 = pp[1], r2 = pp[2], r3 = pp[3];
            float a1 = box_area(r0, r1, r2, r3);
            int g0 = part * (NG / 4);
            for (int g = g0; g < g0 + NG / 4; g++) {
                float v = s_ok[g] ? iou_pair(r0, r1, r2, r3, a1,
                                             s_g[g][0], s_g[g][1], s_g[g][2], s_g[g][3],
                                             s_area[g])
                                  : -1.0f;
                if (v > best_v) { best_v = v; best_g = g; }
            }
        }
        // (v desc, g asc) reduce over the 4 partitions => first-max semantics
        #pragma unroll
        for (int o = 2; o > 0; o >>= 1) {
            float ov = __shfl_down_sync(0xFFFFFFFFu, best_v, o, 4);
            int   og = __shfl_down_sync(0xFFFFFFFFu, best_g, o, 4);
            if (ov > best_v || (ov == best_v && og < best_g)) { best_v = ov; best_g = og; }
        }
        if (part == 0 && roi < PCAP) s_ga[roi] = (roi < np) ? best_g : 0;
    }
    __syncthreads();

    float* rois_out = out + (size_t)b * TROIS * 4;
    float* cls_out  = out + OFF_CLS + (size_t)b * TROIS;
    float* del_out  = out + OFF_DEL + (size_t)b * TROIS * 4;

    if (t < PCAP) {
        float r0 = 0, r1 = 0, r2 = 0, r3 = 0;
        float c = 0, d0 = 0, d1 = 0, d2 = 0, d3 = 0;
        int ga = s_ga[t];
        if (t < np) {
            int n = s_pos_idx[t];
            const float* pp = props + ((size_t)b * NP + n) * 4;
            r0 = pp[0]; r1 = pp[1]; r2 = pp[2]; r3 = pp[3];
            float gy1 = s_g[ga][0], gx1 = s_g[ga][1], gy2 = s_g[ga][2], gx2 = s_g[ga][3];
            float h  = __fsub_rn(r2, r0);
            float w  = __fsub_rn(r3, r1);
            float gh = __fsub_rn(gy2, gy1);
            float gw = __fsub_rn(gx2, gx1);
            float cy  = __fadd_rn(r0,  __fmul_rn(0.5f, h));
            float cx  = __fadd_rn(r1,  __fmul_rn(0.5f, w));
            float gcy = __fadd_rn(gy1, __fmul_rn(0.5f, gh));
            float gcx = __fadd_rn(gx1, __fmul_rn(0.5f, gw));
            d0 = __fdiv_rn(__fdiv_rn(__fsub_rn(gcy, cy), h), 0.1f);
            d1 = __fdiv_rn(__fdiv_rn(__fsub_rn(gcx, cx), w), 0.1f);
            d2 = __fdiv_rn((float)log((double)__fdiv_rn(gh, h)), 0.2f);
            d3 = __fdiv_rn((float)log((double)__fdiv_rn(gw, w)), 0.2f);
            c = (float)s_cls[ga];
        }
        d_gt_assign[b][t] = ga;
        d_pos_roi[b][t][0] = r0; d_pos_roi[b][t][1] = r1;
        d_pos_roi[b][t][2] = r2; d_pos_roi[b][t][3] = r3;
        rois_out[t * 4 + 0] = r0; rois_out[t * 4 + 1] = r1;
        rois_out[t * 4 + 2] = r2; rois_out[t * 4 + 3] = r3;
        cls_out[t] = c;
        del_out[t * 4 + 0] = d0; del_out[t * 4 + 1] = d1;
        del_out[t * 4 + 2] = d2; del_out[t * 4 + 3] = d3;
    } else if (t < TROIS) {
        int j = t - PCAP;
        float r0 = 0, r1 = 0, r2 = 0, r3 = 0;
        if (j < nn) {
            int n = s_neg_idx[j];
            const float* pp = props + ((size_t)b * NP + n) * 4;
            r0 = pp[0]; r1 = pp[1]; r2 = pp[2]; r3 = pp[3];
        }
        rois_out[t * 4 + 0] = r0; rois_out[t * 4 + 1] = r1;
        rois_out[t * 4 + 2] = r2; rois_out[t * 4 + 3] = r3;
        cls_out[t] = 0.0f;
        del_out[t * 4 + 0] = 0.0f; del_out[t * 4 + 1] = 0.0f;
        del_out[t * 4 + 2] = 0.0f; del_out[t * 4 + 3] = 0.0f;
    }
}

// ---------------------------------------------------------------------------
// Kernel 3: mask targets. TWO blocks per (image, roi-slot), 392 threads each
// -> ~5 blocks/SM for maximum scattered-load MLP (L1tex wavefront bound).
// ---------------------------------------------------------------------------
#define MBLK 392
__device__ __forceinline__ float load_mask_val(const void* masks, int kind, size_t idx) {
    if (kind == 0) return (float)__ldg((const unsigned char*)masks + idx);
    if (kind == 1) return (float)__ldg((const int*)masks + idx);
    return __ldg((const float*)masks + idx);
}

__global__ void __launch_bounds__(MBLK) k_masks(const void* __restrict__ masks,
                                                float* __restrict__ out) {
    int part = blockIdx.x & 1;
    int sb   = blockIdx.x >> 1;
    int slot = sb % TROIS;
    int b    = sb / TROIS;
    int p    = part * MBLK + threadIdx.x;     // 0..783
    float* mout = out + OFF_MASK + ((size_t)(b * TROIS + slot)) * MPIX;

    int np = d_num_pos[b];
    if (slot >= np || slot >= PCAP) {
        mout[p] = 0.0f;
        return;
    }
    int kind = d_mask_kind;
    float y1 = d_pos_roi[b][slot][0];
    float x1 = d_pos_roi[b][slot][1];
    float y2 = d_pos_roi[b][slot][2];
    float x2 = d_pos_roi[b][slot][3];
    int g = d_gt_assign[b][slot];
    float dy = __fsub_rn(y2, y1);
    float dx = __fsub_rn(x2, x1);

    int i = p / MS2;
    int j = p % MS2;
    // ys = (y1 + (y2-y1)*i/27) * 1023  — exact jnp op order, IEEE rn
    float ys = __fmul_rn(__fadd_rn(y1, __fdiv_rn(__fmul_rn(dy, (float)i), 27.0f)), 1023.0f);
    float xs = __fmul_rn(__fadd_rn(x1, __fdiv_rn(__fmul_rn(dx, (float)j), 27.0f)), 1023.0f);

    float y0f = fminf(fmaxf(floorf(ys), 0.0f), 1023.0f);
    float x0f = fminf(fmaxf(floorf(xs), 0.0f), 1023.0f);
    int y0 = (int)y0f;
    int x0 = (int)x0f;
    int y1i = (int)fminf(__fadd_rn(y0f, 1.0f), 1023.0f);
    int x1i = (int)fminf(__fadd_rn(x0f, 1.0f), 1023.0f);
    float wy = __fsub_rn(ys, y0f);
    float wx = __fsub_rn(xs, x0f);
    float oy = __fsub_rn(1.0f, wy);
    float ox = __fsub_rn(1.0f, wx);

    size_t base_b = (size_t)b * MH;
    size_t row0 = (base_b + (size_t)y0)  * MW;
    size_t row1 = (base_b + (size_t)y1i) * MW;
    float m00 = load_mask_val(masks, kind, (row0 + x0)  * NG + g);
    float m01 = load_mask_val(masks, kind, (row0 + x1i) * NG + g);
    float m10 = load_mask_val(masks, kind, (row1 + x0)  * NG + g);
    float m11 = load_mask_val(masks, kind, (row1 + x1i) * NG + g);

    float t0 = __fmul_rn(__fmul_rn(m00, oy), ox);
    float t1 = __fmul_rn(__fmul_rn(m01, oy), wx);
    float t2 = __fmul_rn(__fmul_rn(m10, wy), ox);
    float t3 = __fmul_rn(__fmul_rn(m11, wy), wx);
    float val = __fadd_rn(__fadd_rn(__fadd_rn(t0, t1), t2), t3);
    mout[p] = rintf(val);   // round-half-even, matches jnp.round
}

extern "C" void kernel_launch(void* const* d_in, const int* in_sizes, int n_in,
                              void* d_out, int out_size) {
    const float* props = (const float*)d_in[0];
    const int*   gtc   = (const int*)d_in[1];
    const float* gtb   = (const float*)d_in[2];
    const void*  masks = d_in[3];
    float* out = (float*)d_out;

    k_flags<<<BB * CHUNKS + 1, FBLK>>>(props, gtc, gtb, (const unsigned int*)masks);
    k_select_outputs<<<BB, 288>>>(props, gtc, gtb, out);
    k_masks<<<BB * TROIS * 2, MBLK>>>(masks, out);
}